// round 6
// baseline (speedup 1.0000x reference)
#include <cuda_runtime.h>
#include <math.h>
#include <stdint.h>
#include <string.h>

// ---------------- problem constants ----------------
#define N_PTS   29696
#define N_IN_C  1024
#define E1_C    512
#define E2_C    512
#define E3_C    2048
#define NZ_C    32
#define D1_C    2048
#define D2_C    512
#define D3_C    512
#define K_C     100
#define EPS_C   1e-5f

#define MBLK    (N_PTS / 128)                   // 232
#define MSE_PARTIALS (MBLK * (N_IN_C / 128))    // 232*8 = 1856

// z-layer scalar GEMM tiling
#define BM 128
#define BN 64
#define BK 16

// mma.sync GEMM: block tile 128x128, K-chunk 32, 8 warps (2x4), warp tile 64x32
#define ARR_F (128 * 36)                         // floats per smem component array
#define DSMEM3 (6 * ARR_F * 4)                   // 110592 B (3-way: A0A1A2 B0B1B2)
#define DSMEM2 (4 * ARR_F * 4)                   // 73728 B

// ---------------- scratch ----------------
__device__ float g_bufA[(size_t)N_PTS * 2048];
__device__ float g_bufB[(size_t)N_PTS * 2048];
__device__ float g_wt[2048 * 512];
__device__ float g_zbuf[(size_t)N_PTS * NZ_C];
__device__ float g_q[(size_t)K_C * N_PTS];
__device__ int   g_pred[N_PTS];
__device__ float g_Scon[N_PTS];
__device__ float g_u[K_C];
__device__ float g_f[K_C];
__device__ int   g_cnt[K_C];
__device__ float g_S;
__device__ float g_uloss;
__device__ float g_msep[MSE_PARTIALS];
__device__ float g_klp[MBLK];

__global__ void init_kernel() {
    int t = threadIdx.x;
    if (t < K_C) g_cnt[t] = 0;
}

// ---------------- helpers ----------------
__device__ __forceinline__ float tf32r(float x) {
    uint32_t r;
    asm("cvt.rna.tf32.f32 %0, %1;" : "=r"(r) : "f"(x));
    return __uint_as_float(r);
}
__device__ __forceinline__ void mma8(float* d, const uint32_t* a, const uint32_t* b) {
    asm volatile(
        "mma.sync.aligned.m16n8k8.row.col.f32.tf32.tf32.f32 "
        "{%0,%1,%2,%3}, {%4,%5,%6,%7}, {%8,%9}, {%0,%1,%2,%3};"
        : "+f"(d[0]), "+f"(d[1]), "+f"(d[2]), "+f"(d[3])
        : "r"(a[0]), "r"(a[1]), "r"(a[2]), "r"(a[3]), "r"(b[0]), "r"(b[1]));
}

// ---------------- weight transpose: Wt[n][k] = W[k][n] ----------------
__global__ void wtrans(const float* __restrict__ W, float* __restrict__ Wt, int K, int N) {
    __shared__ float sm[32][33];
    const int tx = threadIdx.x, ty = threadIdx.y;
    const int n0 = blockIdx.x * 32, k0 = blockIdx.y * 32;
#pragma unroll
    for (int j = 0; j < 4; j++)
        sm[ty + j * 8][tx] = W[(size_t)(k0 + ty + j * 8) * N + n0 + tx];
    __syncthreads();
#pragma unroll
    for (int j = 0; j < 4; j++)
        Wt[(size_t)(n0 + ty + j * 8) * K + k0 + tx] = sm[tx][ty + j * 8];
}

// ---------------- split-TF32 mma.sync GEMM ----------------
// A [M x K] fp32 row-major, Bt [N x K] fp32 (K-major rows).
// NSPLIT=3: 6-term product (near-exact fp32). NSPLIT=2: 3-term product.
// MODE 0: C = relu(A@Bt^T + bias). MODE 1: MSE vs Xref -> partial (no store).
template <int NSPLIT, int MODE>
__global__ void __launch_bounds__(256, 1) mma_tf(
    const float* __restrict__ A, const float* __restrict__ Bt,
    const float* __restrict__ bias, float* __restrict__ C,
    const float* __restrict__ Xref, float* __restrict__ partial,
    int K, int N)
{
    extern __shared__ float smf[];
    const int tid = threadIdx.x;
    const int wid = tid >> 5;
    const int lane = tid & 31;
    const int warpM = wid >> 2;          // 0..1 -> 64-row half
    const int warpN = wid & 3;           // 0..3 -> 32-col quarter
    const int rowBlock = blockIdx.y * 128;
    const int colBlock = blockIdx.x * 128;

    float d[4][4][4];
#pragma unroll
    for (int mt = 0; mt < 4; mt++)
#pragma unroll
        for (int nt = 0; nt < 4; nt++)
#pragma unroll
            for (int i = 0; i < 4; i++) d[mt][nt][i] = 0.f;

    // fill mapping: row = tid>>1 (0..127), k-offset = (tid&1)*16
    const int fRow = tid >> 1;
    const int fK = (tid & 1) * 16;
    const float* gA = &A[(size_t)(rowBlock + fRow) * K + fK];
    const float* gB = &Bt[(size_t)(colBlock + fRow) * K + fK];
    const int nch = K >> 5;

    float4 pA[4], pB[4];
#pragma unroll
    for (int i = 0; i < 4; i++) {
        pA[i] = *reinterpret_cast<const float4*>(gA + i * 4);
        pB[i] = *reinterpret_cast<const float4*>(gB + i * 4);
    }

    for (int c = 0; c < nch; c++) {
        // split and store current chunk
#pragma unroll
        for (int i = 0; i < 4; i++) {
            const int off = fRow * 36 + fK + i * 4;
            float4 v = pA[i];
            float4 h, m, l;
            h.x = tf32r(v.x); h.y = tf32r(v.y); h.z = tf32r(v.z); h.w = tf32r(v.w);
            if (NSPLIT == 2) {
                l.x = v.x - h.x; l.y = v.y - h.y; l.z = v.z - h.z; l.w = v.w - h.w;
                *reinterpret_cast<float4*>(&smf[0 * ARR_F + off]) = h;
                *reinterpret_cast<float4*>(&smf[1 * ARR_F + off]) = l;
            } else {
                float4 r;
                r.x = v.x - h.x; r.y = v.y - h.y; r.z = v.z - h.z; r.w = v.w - h.w;
                m.x = tf32r(r.x); m.y = tf32r(r.y); m.z = tf32r(r.z); m.w = tf32r(r.w);
                l.x = r.x - m.x; l.y = r.y - m.y; l.z = r.z - m.z; l.w = r.w - m.w;
                *reinterpret_cast<float4*>(&smf[0 * ARR_F + off]) = h;
                *reinterpret_cast<float4*>(&smf[1 * ARR_F + off]) = m;
                *reinterpret_cast<float4*>(&smf[2 * ARR_F + off]) = l;
            }
            v = pB[i];
            h.x = tf32r(v.x); h.y = tf32r(v.y); h.z = tf32r(v.z); h.w = tf32r(v.w);
            if (NSPLIT == 2) {
                l.x = v.x - h.x; l.y = v.y - h.y; l.z = v.z - h.z; l.w = v.w - h.w;
                *reinterpret_cast<float4*>(&smf[2 * ARR_F + off]) = h;
                *reinterpret_cast<float4*>(&smf[3 * ARR_F + off]) = l;
            } else {
                float4 r;
                r.x = v.x - h.x; r.y = v.y - h.y; r.z = v.z - h.z; r.w = v.w - h.w;
                m.x = tf32r(r.x); m.y = tf32r(r.y); m.z = tf32r(r.z); m.w = tf32r(r.w);
                l.x = r.x - m.x; l.y = r.y - m.y; l.z = r.z - m.z; l.w = r.w - m.w;
                *reinterpret_cast<float4*>(&smf[3 * ARR_F + off]) = h;
                *reinterpret_cast<float4*>(&smf[4 * ARR_F + off]) = m;
                *reinterpret_cast<float4*>(&smf[5 * ARR_F + off]) = l;
            }
        }
        __syncthreads();
        // prefetch next chunk (overlaps with compute)
        if (c + 1 < nch) {
#pragma unroll
            for (int i = 0; i < 4; i++) {
                pA[i] = *reinterpret_cast<const float4*>(gA + 32 + i * 4);
                pB[i] = *reinterpret_cast<const float4*>(gB + 32 + i * 4);
            }
            gA += 32; gB += 32;
        }
        // compute 4 k-steps of 8
        const int BBASE = (NSPLIT == 2) ? 2 : 3;
#pragma unroll
        for (int ks = 0; ks < 4; ks++) {
            uint32_t bf[NSPLIT][4][2];
#pragma unroll
            for (int nt = 0; nt < 4; nt++) {
                const int boff = (warpN * 32 + nt * 8 + (lane >> 2)) * 36 + ks * 8 + (lane & 3);
#pragma unroll
                for (int cc = 0; cc < NSPLIT; cc++) {
                    bf[cc][nt][0] = __float_as_uint(smf[(BBASE + cc) * ARR_F + boff]);
                    bf[cc][nt][1] = __float_as_uint(smf[(BBASE + cc) * ARR_F + boff + 4]);
                }
            }
#pragma unroll
            for (int mt = 0; mt < 4; mt++) {
                const int aoff = (warpM * 64 + mt * 16 + (lane >> 2)) * 36 + ks * 8 + (lane & 3);
                uint32_t af[NSPLIT][4];
#pragma unroll
                for (int cc = 0; cc < NSPLIT; cc++) {
                    af[cc][0] = __float_as_uint(smf[cc * ARR_F + aoff]);
                    af[cc][1] = __float_as_uint(smf[cc * ARR_F + aoff + 8 * 36]);
                    af[cc][2] = __float_as_uint(smf[cc * ARR_F + aoff + 4]);
                    af[cc][3] = __float_as_uint(smf[cc * ARR_F + aoff + 8 * 36 + 4]);
                }
#pragma unroll
                for (int nt = 0; nt < 4; nt++) {
                    if (NSPLIT == 2) {
                        mma8(d[mt][nt], af[0], bf[1][nt]);   // h*l
                        mma8(d[mt][nt], af[1], bf[0][nt]);   // l*h
                        mma8(d[mt][nt], af[0], bf[0][nt]);   // h*h
                    } else {
                        mma8(d[mt][nt], af[0], bf[2][nt]);   // h*l
                        mma8(d[mt][nt], af[2], bf[0][nt]);   // l*h
                        mma8(d[mt][nt], af[1], bf[1][nt]);   // m*m
                        mma8(d[mt][nt], af[0], bf[1][nt]);   // h*m
                        mma8(d[mt][nt], af[1], bf[0][nt]);   // m*h
                        mma8(d[mt][nt], af[0], bf[0][nt]);   // h*h
                    }
                }
            }
        }
        __syncthreads();
    }

    // epilogue
    float2 bb[4];
#pragma unroll
    for (int nt = 0; nt < 4; nt++)
        bb[nt] = *reinterpret_cast<const float2*>(
            &bias[colBlock + warpN * 32 + nt * 8 + (lane & 3) * 2]);

    if (MODE == 0) {
#pragma unroll
        for (int mt = 0; mt < 4; mt++) {
            const int r0 = rowBlock + warpM * 64 + mt * 16 + (lane >> 2);
#pragma unroll
            for (int nt = 0; nt < 4; nt++) {
                const int col = colBlock + warpN * 32 + nt * 8 + (lane & 3) * 2;
                float2 v0, v1;
                v0.x = fmaxf(d[mt][nt][0] + bb[nt].x, 0.f);
                v0.y = fmaxf(d[mt][nt][1] + bb[nt].y, 0.f);
                v1.x = fmaxf(d[mt][nt][2] + bb[nt].x, 0.f);
                v1.y = fmaxf(d[mt][nt][3] + bb[nt].y, 0.f);
                *reinterpret_cast<float2*>(&C[(size_t)r0 * N + col]) = v0;
                *reinterpret_cast<float2*>(&C[(size_t)(r0 + 8) * N + col]) = v1;
            }
        }
    } else {
        float msum = 0.f;
#pragma unroll
        for (int mt = 0; mt < 4; mt++) {
            const int r0 = rowBlock + warpM * 64 + mt * 16 + (lane >> 2);
#pragma unroll
            for (int nt = 0; nt < 4; nt++) {
                const int col = colBlock + warpN * 32 + nt * 8 + (lane & 3) * 2;
                float2 x0 = *reinterpret_cast<const float2*>(&Xref[(size_t)r0 * N + col]);
                float2 x1 = *reinterpret_cast<const float2*>(&Xref[(size_t)(r0 + 8) * N + col]);
                float e;
                e = d[mt][nt][0] + bb[nt].x - x0.x; msum = fmaf(e, e, msum);
                e = d[mt][nt][1] + bb[nt].y - x0.y; msum = fmaf(e, e, msum);
                e = d[mt][nt][2] + bb[nt].x - x1.x; msum = fmaf(e, e, msum);
                e = d[mt][nt][3] + bb[nt].y - x1.y; msum = fmaf(e, e, msum);
            }
        }
        float* red = smf;
        red[tid] = msum;
        __syncthreads();
        for (int o = 128; o > 0; o >>= 1) {
            if (tid < o) red[tid] += red[tid + o];
            __syncthreads();
        }
        if (tid == 0) partial[blockIdx.y * gridDim.x + blockIdx.x] = red[0];
    }
}

// ---------------- small-N fp32 scalar GEMM (z layer, N=32) ----------------
__global__ __launch_bounds__(256) void gemm_relu(
    const float* __restrict__ A, const float* __restrict__ W,
    const float* __restrict__ bias, float* __restrict__ C,
    int M, int K, int N, int doRelu)
{
    __shared__ float As[BK][BM];
    __shared__ float Wsm[BK][BN];
    const int tid = threadIdx.x;
    const int rowBlock = blockIdx.y * BM;
    const int colBlock = blockIdx.x * BN;
    const int tx = tid & 15;
    const int ty = tid >> 4;
    const int rBase = ty * 8;
    const int cBase = tx * 4;

    float acc[8][4];
#pragma unroll
    for (int i = 0; i < 8; i++)
#pragma unroll
        for (int j = 0; j < 4; j++) acc[i][j] = 0.f;

    const int aRow0 = tid >> 2;
    const int aF4   = tid & 3;
    const int wK    = tid >> 4;
    const int wC    = (tid & 15) * 4;

    for (int k0 = 0; k0 < K; k0 += BK) {
#pragma unroll
        for (int h = 0; h < 2; h++) {
            int r = aRow0 + h * 64;
            float4 v = *reinterpret_cast<const float4*>(
                &A[(size_t)(rowBlock + r) * K + k0 + aF4 * 4]);
            As[aF4 * 4 + 0][r] = v.x;
            As[aF4 * 4 + 1][r] = v.y;
            As[aF4 * 4 + 2][r] = v.z;
            As[aF4 * 4 + 3][r] = v.w;
        }
        {
            int col = colBlock + wC;
            float4 v = make_float4(0.f, 0.f, 0.f, 0.f);
            if (col + 3 < N) {
                v = *reinterpret_cast<const float4*>(&W[(size_t)(k0 + wK) * N + col]);
            } else {
                float tmp[4] = {0.f, 0.f, 0.f, 0.f};
                for (int j = 0; j < 4; j++)
                    if (col + j < N) tmp[j] = W[(size_t)(k0 + wK) * N + col + j];
                v = make_float4(tmp[0], tmp[1], tmp[2], tmp[3]);
            }
            *reinterpret_cast<float4*>(&Wsm[wK][wC]) = v;
        }
        __syncthreads();
#pragma unroll
        for (int kk = 0; kk < BK; kk++) {
            float a[8], b[4];
#pragma unroll
            for (int i = 0; i < 8; i++) a[i] = As[kk][rBase + i];
#pragma unroll
            for (int j = 0; j < 4; j++) b[j] = Wsm[kk][cBase + j];
#pragma unroll
            for (int i = 0; i < 8; i++)
#pragma unroll
                for (int j = 0; j < 4; j++) acc[i][j] = fmaf(a[i], b[j], acc[i][j]);
        }
        __syncthreads();
    }
#pragma unroll
    for (int i = 0; i < 8; i++) {
        int row = rowBlock + rBase + i;
#pragma unroll
        for (int j = 0; j < 4; j++) {
            int col = colBlock + cBase + j;
            if (col < N) {
                float v = acc[i][j] + bias[col];
                if (doRelu) v = fmaxf(v, 0.f);
                C[(size_t)row * N + col] = v;
            }
        }
    }
}

// ---------------- pass A ----------------
__global__ __launch_bounds__(128) void passA(
    const float* __restrict__ z, const float* __restrict__ t1,
    const float* __restrict__ clus, float* __restrict__ q,
    int* __restrict__ pred, float* __restrict__ scon,
    float* __restrict__ out, int out_size)
{
    __shared__ float cs[K_C * NZ_C];
    const int tid = threadIdx.x;
    for (int i = tid; i < K_C * NZ_C; i += 128) cs[i] = clus[i];
    __syncthreads();

    const int n = blockIdx.x * 128 + tid;
    if (n >= N_PTS) return;

    const float tx = t1[n * 3 + 0] * 0.01f;
    const float ty = t1[n * 3 + 1] * 0.01f;
    const float tz = t1[n * 3 + 2] * 0.01f;
    const float cm = tx * ty * tz * 0.99f + 1.0f;

    float zp[NZ_C];
    const float* zr = &z[(size_t)n * NZ_C];
    float mean = 0.f;
#pragma unroll
    for (int i = 0; i < NZ_C; i++) { zp[i] = zr[i] * cm; mean += zp[i]; }
    mean *= (1.0f / NZ_C);
    float var = 0.f;
#pragma unroll
    for (int i = 0; i < NZ_C; i++) { float dd = zp[i] - mean; var += dd * dd; }
    var *= (1.0f / (NZ_C - 1));
    const float invstd = 1.0f / sqrtf(var);
#pragma unroll
    for (int i = 0; i < NZ_C; i++) zp[i] = (zp[i] - mean) * invstd;

    float qsum = 0.f;
    float best = -1.f;
    int bestk = 0;
    for (int k = 0; k < K_C; k++) {
        const float* c = &cs[k * NZ_C];
        float dsum = 0.f;
#pragma unroll
        for (int i = 0; i < NZ_C; i++) { float df = zp[i] - c[i]; dsum = fmaf(df, df, dsum); }
        float qr = EPS_C + dsum;
        q[(size_t)k * N_PTS + n] = qr;
        qsum += qr;
        if (qr > best) { best = qr; bestk = k; }
    }
    const float inv = 1.0f / qsum;
    float s = 0.f;
    for (int k = 0; k < K_C; k++) {
        float qn = q[(size_t)k * N_PTS + n] * inv;
        q[(size_t)k * N_PTS + n] = qn;
        float l = logf(qn);
        float t = 1.0f - qn;
        float neg_temp = t * t * (-l) * (float)N_PTS;
        s += 1.0f / sqrtf(neg_temp);
    }
    pred[n] = bestk;
    scon[n] = s;
    if (n < out_size) out[n] = (float)bestk;
    atomicAdd(&g_cnt[bestk], 1);
}

// ---------------- reductions ----------------
__global__ void ureduce(const float* __restrict__ q) {
    __shared__ float sh[256];
    const int k = blockIdx.x;
    float s = 0.f;
    for (int n = threadIdx.x; n < N_PTS; n += 256) s += q[(size_t)k * N_PTS + n];
    sh[threadIdx.x] = s;
    __syncthreads();
    for (int o = 128; o > 0; o >>= 1) {
        if (threadIdx.x < o) sh[threadIdx.x] += sh[threadIdx.x + o];
        __syncthreads();
    }
    if (threadIdx.x == 0) g_u[k] = sh[0];
}

__global__ void sreduce(const float* __restrict__ scon) {
    __shared__ float sh[256];
    float s = 0.f;
    for (int n = threadIdx.x; n < N_PTS; n += 256) s += scon[n];
    sh[threadIdx.x] = s;
    __syncthreads();
    for (int o = 128; o > 0; o >>= 1) {
        if (threadIdx.x < o) sh[threadIdx.x] += sh[threadIdx.x + o];
        __syncthreads();
    }
    if (threadIdx.x == 0) g_S = sh[0];
}

__global__ void passB(const float* __restrict__ clus) {
    __shared__ float sh[256];
    const int tid = threadIdx.x;
    float s = 0.f;
    for (int p = tid; p < K_C * K_C; p += 256) {
        int i = p / K_C, j = p - i * K_C;
        const float* a = &clus[i * NZ_C];
        const float* b = &clus[j * NZ_C];
        float dsum = 0.f;
#pragma unroll
        for (int t = 0; t < NZ_C; t++) { float df = a[t] - b[t]; dsum = fmaf(df, df, dsum); }
        s += dsum;
    }
    sh[tid] = s;
    __syncthreads();
    for (int o = 128; o > 0; o >>= 1) {
        if (tid < o) sh[tid] += sh[tid + o];
        __syncthreads();
    }
    if (tid == 0) {
        float md = sh[0] / (float)(K_C * K_C - K_C);
        g_uloss = 0.01f / md;

        float un[K_C], vn[K_C];
        float um = 0.f;
        for (int k = 0; k < K_C; k++) um += g_u[k];
        um /= (float)K_C;
        float uv = 0.f;
        for (int k = 0; k < K_C; k++) { float dd = g_u[k] - um; uv += dd * dd; }
        uv /= (float)(K_C - 1);
        float uis = 1.0f / sqrtf(uv);
        for (int k = 0; k < K_C; k++) un[k] = (g_u[k] - um) * uis;

        float S = g_S;
        float vm = 0.f;
        for (int k = 0; k < K_C; k++) {
            float nc = (g_cnt[k] > 0) ? (float)g_cnt[k] : 1.0f;
            vn[k] = sqrtf(nc) * S;
            vm += vn[k];
        }
        vm /= (float)K_C;
        float vv = 0.f;
        for (int k = 0; k < K_C; k++) { float dd = vn[k] - vm; vv += dd * dd; }
        vv /= (float)(K_C - 1);
        float vis = 1.0f / sqrtf(vv);
        for (int k = 0; k < K_C; k++) vn[k] = (vn[k] - vm) * vis;

        float umin = un[0], vmin = vn[0];
        for (int k = 1; k < K_C; k++) {
            umin = fminf(umin, un[k]);
            vmin = fminf(vmin, vn[k]);
        }
        for (int k = 0; k < K_C; k++) {
            g_f[k] = (un[k] - umin + 0.001f) + (vn[k] - vmin + 0.001f) + 1.0f;
        }
    }
}

__global__ __launch_bounds__(128) void passC(const float* __restrict__ q,
                                             float* __restrict__ klp) {
    __shared__ float fsh[K_C];
    __shared__ float sh[128];
    const int tid = threadIdx.x;
    for (int i = tid; i < K_C; i += 128) fsh[i] = g_f[i];
    __syncthreads();
    const int n = blockIdx.x * 128 + tid;
    float kl = 0.f;
    float ws = 0.f;
    for (int k = 0; k < K_C; k++) {
        float qv = q[(size_t)k * N_PTS + n];
        ws += qv * qv / fsh[k];
    }
    float inv = 1.0f / ws;
    for (int k = 0; k < K_C; k++) {
        float qv = q[(size_t)k * N_PTS + n];
        float p = qv * qv / fsh[k] * inv;
        kl += p * (logf(p) - logf(qv));
    }
    sh[tid] = kl;
    __syncthreads();
    for (int o = 64; o > 0; o >>= 1) {
        if (tid < o) sh[tid] += sh[tid + o];
        __syncthreads();
    }
    if (tid == 0) klp[blockIdx.x] = sh[0];
}

__global__ void finalk(float* __restrict__ out, int out_size) {
    __shared__ float sh[256];
    __shared__ float tot[2];
    const int tid = threadIdx.x;
    float s = 0.f;
    for (int i = tid; i < MSE_PARTIALS; i += 256) s += g_msep[i];
    sh[tid] = s;
    __syncthreads();
    for (int o = 128; o > 0; o >>= 1) {
        if (tid < o) sh[tid] += sh[tid + o];
        __syncthreads();
    }
    if (tid == 0) tot[0] = sh[0];
    __syncthreads();
    s = 0.f;
    for (int i = tid; i < MBLK; i += 256) s += g_klp[i];
    sh[tid] = s;
    __syncthreads();
    for (int o = 128; o > 0; o >>= 1) {
        if (tid < o) sh[tid] += sh[tid + o];
        __syncthreads();
    }
    if (tid == 0) tot[1] = sh[0];
    __syncthreads();
    if (tid == 0) {
        float re_loss = tot[0] / ((float)N_PTS * (float)N_IN_C);
        float kl_loss = tot[1] / ((float)N_PTS * (float)K_C) * 0.01f;
        float loss = kl_loss + re_loss + g_uloss;
        if (out_size > N_PTS) out[N_PTS] = loss;
    }
}

// ---------------- launch ----------------
extern "C" void kernel_launch(void* const* d_in, const int* in_sizes, int n_in,
                              void* d_out, int out_size) {
    const float* x    = (const float*)d_in[0];
    const float* t1   = (const float*)d_in[1];
    const float* clus = (const float*)d_in[2];
    const float* We1  = (const float*)d_in[3];
    const float* be1  = (const float*)d_in[4];
    const float* We2  = (const float*)d_in[5];
    const float* be2  = (const float*)d_in[6];
    const float* We3  = (const float*)d_in[7];
    const float* be3  = (const float*)d_in[8];
    const float* Wz   = (const float*)d_in[9];
    const float* bz   = (const float*)d_in[10];
    const float* Wd1  = (const float*)d_in[11];
    const float* bd1  = (const float*)d_in[12];
    const float* Wd2  = (const float*)d_in[13];
    const float* bd2  = (const float*)d_in[14];
    const float* Wd3  = (const float*)d_in[15];
    const float* bd3  = (const float*)d_in[16];
    const float* Wxb  = (const float*)d_in[17];
    const float* bxb  = (const float*)d_in[18];
    float* out = (float*)d_out;

    float *bufA, *bufB, *wt, *zbuf, *qbuf, *scon, *msep, *klp;
    int *pred;
    cudaGetSymbolAddress((void**)&bufA, g_bufA);
    cudaGetSymbolAddress((void**)&bufB, g_bufB);
    cudaGetSymbolAddress((void**)&wt,   g_wt);
    cudaGetSymbolAddress((void**)&zbuf, g_zbuf);
    cudaGetSymbolAddress((void**)&qbuf, g_q);
    cudaGetSymbolAddress((void**)&pred, g_pred);
    cudaGetSymbolAddress((void**)&scon, g_Scon);
    cudaGetSymbolAddress((void**)&msep, g_msep);
    cudaGetSymbolAddress((void**)&klp,  g_klp);

    cudaFuncSetAttribute(mma_tf<3, 0>, cudaFuncAttributeMaxDynamicSharedMemorySize, DSMEM3);
    cudaFuncSetAttribute(mma_tf<2, 0>, cudaFuncAttributeMaxDynamicSharedMemorySize, DSMEM2);
    cudaFuncSetAttribute(mma_tf<2, 1>, cudaFuncAttributeMaxDynamicSharedMemorySize, DSMEM2);

    init_kernel<<<1, 128>>>();
    const dim3 tb(32, 8);

    // encoder: 6-term (near-exact fp32) — feeds predict via z
    wtrans<<<dim3(E1_C / 32, N_IN_C / 32), tb>>>(We1, wt, N_IN_C, E1_C);
    mma_tf<3, 0><<<dim3(E1_C / 128, MBLK), 256, DSMEM3>>>(x, wt, be1, bufA, nullptr, nullptr, N_IN_C, E1_C);
    wtrans<<<dim3(E2_C / 32, E1_C / 32), tb>>>(We2, wt, E1_C, E2_C);
    mma_tf<3, 0><<<dim3(E2_C / 128, MBLK), 256, DSMEM3>>>(bufA, wt, be2, bufB, nullptr, nullptr, E1_C, E2_C);
    wtrans<<<dim3(E3_C / 32, E2_C / 32), tb>>>(We3, wt, E2_C, E3_C);
    mma_tf<3, 0><<<dim3(E3_C / 128, MBLK), 256, DSMEM3>>>(bufB, wt, be3, bufA, nullptr, nullptr, E2_C, E3_C);
    gemm_relu<<<dim3(1, N_PTS / BM), 256>>>(bufA, Wz, bz, zbuf, N_PTS, E3_C, NZ_C, 0);

    // decoder: 3-term (feeds only re_loss)
    wtrans<<<dim3(D1_C / 32, NZ_C / 32), tb>>>(Wd1, wt, NZ_C, D1_C);
    mma_tf<2, 0><<<dim3(D1_C / 128, MBLK), 256, DSMEM2>>>(zbuf, wt, bd1, bufB, nullptr, nullptr, NZ_C, D1_C);
    wtrans<<<dim3(D2_C / 32, D1_C / 32), tb>>>(Wd2, wt, D1_C, D2_C);
    mma_tf<2, 0><<<dim3(D2_C / 128, MBLK), 256, DSMEM2>>>(bufB, wt, bd2, bufA, nullptr, nullptr, D1_C, D2_C);
    wtrans<<<dim3(D3_C / 32, D2_C / 32), tb>>>(Wd3, wt, D2_C, D3_C);
    mma_tf<2, 0><<<dim3(D3_C / 128, MBLK), 256, DSMEM2>>>(bufA, wt, bd3, bufB, nullptr, nullptr, D2_C, D3_C);
    wtrans<<<dim3(N_IN_C / 32, D3_C / 32), tb>>>(Wxb, wt, D3_C, N_IN_C);
    mma_tf<2, 1><<<dim3(N_IN_C / 128, MBLK), 256, DSMEM2>>>(bufB, wt, bxb, nullptr, x, msep, D3_C, N_IN_C);

    // clustering + losses
    passA<<<MBLK, 128>>>(zbuf, t1, clus, qbuf, pred, scon, out, out_size);
    ureduce<<<K_C, 256>>>(qbuf);
    sreduce<<<1, 256>>>(scon);
    passB<<<1, 256>>>(clus);
    passC<<<MBLK, 128>>>(qbuf, klp);
    finalk<<<1, 256>>>(out, out_size);
}

// round 7
// speedup vs baseline: 1.0611x; 1.0611x over previous
#include <cuda_runtime.h>
#include <math.h>
#include <stdint.h>
#include <string.h>

// ---------------- problem constants ----------------
#define N_PTS   29696
#define N_IN_C  1024
#define E1_C    512
#define E2_C    512
#define E3_C    2048
#define NZ_C    32
#define D1_C    2048
#define D2_C    512
#define D3_C    512
#define K_C     100
#define EPS_C   1e-5f

#define MBLK    (N_PTS / 128)                   // 232
#define MSE_PARTIALS (MBLK * (N_IN_C / 128))    // 1856

// z-layer scalar GEMM tiling
#define BM 128
#define BN 64
#define BK 16

// ---------------- scratch ----------------
__device__ float g_bufA[(size_t)N_PTS * 2048];
__device__ float g_bufB[(size_t)N_PTS * 2048];
__device__ float g_cA0[(size_t)N_PTS * 2048];   // A component buffers (fragment-major)
__device__ float g_cA1[(size_t)N_PTS * 2048];
__device__ float g_cA2[(size_t)N_PTS * 1024];   // 3rd comp only used for K<=1024 (encoder)
__device__ float g_cB0[2048 * 512];             // B component buffers (weights)
__device__ float g_cB1[2048 * 512];
__device__ float g_cB2[2048 * 512];
__device__ float g_zbuf[(size_t)N_PTS * NZ_C];
__device__ float g_q[(size_t)K_C * N_PTS];
__device__ int   g_pred[N_PTS];
__device__ float g_Scon[N_PTS];
__device__ float g_u[K_C];
__device__ float g_f[K_C];
__device__ int   g_cnt[K_C];
__device__ float g_S;
__device__ float g_uloss;
__device__ float g_msep[MSE_PARTIALS];
__device__ float g_klp[MBLK];

__global__ void init_kernel() {
    int t = threadIdx.x;
    if (t < K_C) g_cnt[t] = 0;
}

// ---------------- helpers ----------------
__device__ __forceinline__ float tf32r(float x) {
    uint32_t r;
    asm("cvt.rna.tf32.f32 %0, %1;" : "=r"(r) : "f"(x));
    return __uint_as_float(r);
}
__device__ __forceinline__ void mma8(float* d, const uint32_t* a, const uint32_t* b) {
    asm volatile(
        "mma.sync.aligned.m16n8k8.row.col.f32.tf32.tf32.f32 "
        "{%0,%1,%2,%3}, {%4,%5,%6,%7}, {%8,%9}, {%0,%1,%2,%3};"
        : "+f"(d[0]), "+f"(d[1]), "+f"(d[2]), "+f"(d[3])
        : "r"(a[0]), "r"(a[1]), "r"(a[2]), "r"(a[3]), "r"(b[0]), "r"(b[1]));
}
__device__ __forceinline__ void cpa16(uint32_t dst_smem, const float* src) {
    asm volatile("cp.async.cg.shared.global [%0], [%1], 16;"
                 :: "r"(dst_smem), "l"(__cvta_generic_to_global(src)));
}
union F4U { float4 f; uint32_t u[4]; };
union F2U { float2 f; uint32_t u[2]; };

// ---------------- split kernels ----------------
// A comp layout: [M/16][K/8] tiles of 32 lanes x float4 (128 floats).
// lane = (m&7)*4 + (k&3); slot = ((m>>3)&1) + 2*((k>>2)&1)
template <int NSPLIT>
__global__ void splitA(const float* __restrict__ src, float* __restrict__ c0,
                       float* __restrict__ c1, float* __restrict__ c2,
                       int MK, int logK) {
    int idx = blockIdx.x * 256 + threadIdx.x;
    if (idx >= MK) return;
    float v = src[idx];
    int k = idx & ((1 << logK) - 1);
    int m = idx >> logK;
    int tile = (m >> 4) * (1 << (logK - 3)) + (k >> 3);
    int lane = (m & 7) * 4 + (k & 3);
    int slot = ((m >> 3) & 1) + 2 * ((k >> 2) & 1);
    int off = tile * 128 + lane * 4 + slot;
    float h = tf32r(v);
    float r = v - h;
    if (NSPLIT == 2) {
        c0[off] = h; c1[off] = r;
    } else {
        float mm = tf32r(r);
        c0[off] = h; c1[off] = mm; c2[off] = r - mm;
    }
}

// B comp layout: [N/8][K/8] tiles of 32 lanes x float2 (64 floats).
// from W[k][n]: lane = (n&7)*4 + (k&3); slot = (k>>2)&1
template <int NSPLIT>
__global__ void splitB(const float* __restrict__ W, float* __restrict__ c0,
                       float* __restrict__ c1, float* __restrict__ c2,
                       int KN, int logN, int Kdim) {
    int idx = blockIdx.x * 256 + threadIdx.x;
    if (idx >= KN) return;
    float v = W[idx];
    int n = idx & ((1 << logN) - 1);
    int k = idx >> logN;
    int tile = (n >> 3) * (Kdim >> 3) + (k >> 3);
    int lane = (n & 7) * 4 + (k & 3);
    int slot = (k >> 2) & 1;
    int off = tile * 64 + lane * 2 + slot;
    float h = tf32r(v);
    float r = v - h;
    if (NSPLIT == 2) {
        c0[off] = h; c1[off] = r;
    } else {
        float mm = tf32r(r);
        c0[off] = h; c1[off] = mm; c2[off] = r - mm;
    }
}

// ---------------- pipelined split-TF32 mma GEMM ----------------
// Block tile 128x128, K-chunk 32, 8 warps (warpM 0..1 x warpN 0..3).
// Stage floats: NSPLIT*4096 (A) + NSPLIT*4096 (B)
template <int NSPLIT, int MODE>
__global__ void __launch_bounds__(256, 1) mma_pipe(
    const float* __restrict__ A0, const float* __restrict__ A1, const float* __restrict__ A2,
    const float* __restrict__ B0, const float* __restrict__ B1, const float* __restrict__ B2,
    const float* __restrict__ bias, float* __restrict__ C,
    const float* __restrict__ Xref, float* __restrict__ partial,
    int K, int N)
{
    extern __shared__ float smf[];
    const int STAGE_F = NSPLIT * 8192;
    const int tid = threadIdx.x;
    const int wid = tid >> 5;
    const int lane = tid & 31;
    const int warpM = wid >> 2;
    const int warpN = wid & 3;
    const int rowBlock = blockIdx.y * 128;
    const int colBlock = blockIdx.x * 128;
    const int rowTile = rowBlock >> 4;   // /16
    const int colTile = colBlock >> 3;   // /8
    const int ktiles = K >> 3;
    const int nch = K >> 5;

    const float* Ac[3] = { A0, A1, A2 };
    const float* Bc[3] = { B0, B1, B2 };
    const uint32_t smem_base = (uint32_t)__cvta_generic_to_shared(smf);

    float d[4][4][4];
#pragma unroll
    for (int mt = 0; mt < 4; mt++)
#pragma unroll
        for (int nt = 0; nt < 4; nt++)
#pragma unroll
            for (int i = 0; i < 4; i++) d[mt][nt][i] = 0.f;

    // ---- async stage copy ----
    auto copy_stage = [&](int s, int c) {
        const uint32_t sbA = smem_base + (uint32_t)(s * STAGE_F) * 4u;
        const uint32_t sbB = sbA + (uint32_t)(NSPLIT * 4096) * 4u;
#pragma unroll
        for (int cc = 0; cc < NSPLIT; cc++) {
            const float* srcA = Ac[cc];
            const float* srcB = Bc[cc];
#pragma unroll
            for (int j = 0; j < 4; j++) {
                int u = tid + j * 256;                 // 0..1023
                int mt = u >> 7, restA = u & 127;      // A: 8 mtiles x 128 units
                cpa16(sbA + (uint32_t)(cc * 4096 + u * 4) * 4u,
                      srcA + ((size_t)(rowTile + mt) * ktiles + 4 * c) * 128 + restA * 4);
                int nt = u >> 6, restB = u & 63;       // B: 16 ntiles x 64 units
                cpa16(sbB + (uint32_t)(cc * 4096 + u * 4) * 4u,
                      srcB + ((size_t)(colTile + nt) * ktiles + 4 * c) * 64 + restB * 4);
            }
        }
    };

    // ---- compute one stage ----
    auto compute_stage = [&](int s) {
        const float* sA = smf + s * STAGE_F;
        const float* sB = sA + NSPLIT * 4096;
#pragma unroll
        for (int ks = 0; ks < 4; ks++) {
            F2U bf[3][4];
#pragma unroll
            for (int nt = 0; nt < 4; nt++)
#pragma unroll
                for (int cc = 0; cc < NSPLIT; cc++)
                    bf[cc][nt].f = *reinterpret_cast<const float2*>(
                        &sB[cc * 4096 + (((warpN * 4 + nt) * 4 + ks) * 32 + lane) * 2]);
#pragma unroll
            for (int mt = 0; mt < 4; mt++) {
                F4U af[3];
#pragma unroll
                for (int cc = 0; cc < NSPLIT; cc++)
                    af[cc].f = *reinterpret_cast<const float4*>(
                        &sA[cc * 4096 + (((warpM * 4 + mt) * 4 + ks) * 32 + lane) * 4]);
#pragma unroll
                for (int nt = 0; nt < 4; nt++) {
                    if (NSPLIT == 2) {
                        mma8(d[mt][nt], af[0].u, bf[1][nt].u);   // h*l
                        mma8(d[mt][nt], af[1].u, bf[0][nt].u);   // l*h
                        mma8(d[mt][nt], af[0].u, bf[0][nt].u);   // h*h
                    } else {
                        mma8(d[mt][nt], af[0].u, bf[2][nt].u);   // h*l
                        mma8(d[mt][nt], af[2].u, bf[0][nt].u);   // l*h
                        mma8(d[mt][nt], af[1].u, bf[1][nt].u);   // m*m
                        mma8(d[mt][nt], af[0].u, bf[1][nt].u);   // h*m
                        mma8(d[mt][nt], af[1].u, bf[0][nt].u);   // m*h
                        mma8(d[mt][nt], af[0].u, bf[0][nt].u);   // h*h
                    }
                }
            }
        }
    };

    // ---- pipelined mainloop ----
    copy_stage(0, 0);
    asm volatile("cp.async.commit_group;" ::: "memory");
    if (nch > 1) {
        copy_stage(1, 1);
        asm volatile("cp.async.commit_group;" ::: "memory");
    }
    for (int c = 0; c < nch; c++) {
        if (c + 1 < nch)
            asm volatile("cp.async.wait_group 1;" ::: "memory");
        else
            asm volatile("cp.async.wait_group 0;" ::: "memory");
        __syncthreads();
        compute_stage(c & 1);
        if (c + 2 < nch) {
            __syncthreads();
            copy_stage(c & 1, c + 2);
            asm volatile("cp.async.commit_group;" ::: "memory");
        }
    }

    // ---- epilogue (identical math to proven R6) ----
    float2 bb[4];
#pragma unroll
    for (int nt = 0; nt < 4; nt++)
        bb[nt] = *reinterpret_cast<const float2*>(
            &bias[colBlock + warpN * 32 + nt * 8 + (lane & 3) * 2]);

    if (MODE == 0) {
#pragma unroll
        for (int mt = 0; mt < 4; mt++) {
            const int r0 = rowBlock + warpM * 64 + mt * 16 + (lane >> 2);
#pragma unroll
            for (int nt = 0; nt < 4; nt++) {
                const int col = colBlock + warpN * 32 + nt * 8 + (lane & 3) * 2;
                float2 v0, v1;
                v0.x = fmaxf(d[mt][nt][0] + bb[nt].x, 0.f);
                v0.y = fmaxf(d[mt][nt][1] + bb[nt].y, 0.f);
                v1.x = fmaxf(d[mt][nt][2] + bb[nt].x, 0.f);
                v1.y = fmaxf(d[mt][nt][3] + bb[nt].y, 0.f);
                *reinterpret_cast<float2*>(&C[(size_t)r0 * N + col]) = v0;
                *reinterpret_cast<float2*>(&C[(size_t)(r0 + 8) * N + col]) = v1;
            }
        }
    } else {
        float msum = 0.f;
#pragma unroll
        for (int mt = 0; mt < 4; mt++) {
            const int r0 = rowBlock + warpM * 64 + mt * 16 + (lane >> 2);
#pragma unroll
            for (int nt = 0; nt < 4; nt++) {
                const int col = colBlock + warpN * 32 + nt * 8 + (lane & 3) * 2;
                float2 x0 = *reinterpret_cast<const float2*>(&Xref[(size_t)r0 * N + col]);
                float2 x1 = *reinterpret_cast<const float2*>(&Xref[(size_t)(r0 + 8) * N + col]);
                float e;
                e = d[mt][nt][0] + bb[nt].x - x0.x; msum = fmaf(e, e, msum);
                e = d[mt][nt][1] + bb[nt].y - x0.y; msum = fmaf(e, e, msum);
                e = d[mt][nt][2] + bb[nt].x - x1.x; msum = fmaf(e, e, msum);
                e = d[mt][nt][3] + bb[nt].y - x1.y; msum = fmaf(e, e, msum);
            }
        }
        __syncthreads();
        float* red = smf;
        red[tid] = msum;
        __syncthreads();
        for (int o = 128; o > 0; o >>= 1) {
            if (tid < o) red[tid] += red[tid + o];
            __syncthreads();
        }
        if (tid == 0) partial[blockIdx.y * gridDim.x + blockIdx.x] = red[0];
    }
}

// ---------------- small-N fp32 scalar GEMM (z layer, N=32) ----------------
__global__ __launch_bounds__(256) void gemm_relu(
    const float* __restrict__ A, const float* __restrict__ W,
    const float* __restrict__ bias, float* __restrict__ C,
    int M, int K, int N, int doRelu)
{
    __shared__ float As[BK][BM];
    __shared__ float Wsm[BK][BN];
    const int tid = threadIdx.x;
    const int rowBlock = blockIdx.y * BM;
    const int colBlock = blockIdx.x * BN;
    const int tx = tid & 15;
    const int ty = tid >> 4;
    const int rBase = ty * 8;
    const int cBase = tx * 4;

    float acc[8][4];
#pragma unroll
    for (int i = 0; i < 8; i++)
#pragma unroll
        for (int j = 0; j < 4; j++) acc[i][j] = 0.f;

    const int aRow0 = tid >> 2;
    const int aF4   = tid & 3;
    const int wK    = tid >> 4;
    const int wC    = (tid & 15) * 4;

    for (int k0 = 0; k0 < K; k0 += BK) {
#pragma unroll
        for (int h = 0; h < 2; h++) {
            int r = aRow0 + h * 64;
            float4 v = *reinterpret_cast<const float4*>(
                &A[(size_t)(rowBlock + r) * K + k0 + aF4 * 4]);
            As[aF4 * 4 + 0][r] = v.x;
            As[aF4 * 4 + 1][r] = v.y;
            As[aF4 * 4 + 2][r] = v.z;
            As[aF4 * 4 + 3][r] = v.w;
        }
        {
            int col = colBlock + wC;
            float4 v = make_float4(0.f, 0.f, 0.f, 0.f);
            if (col + 3 < N) {
                v = *reinterpret_cast<const float4*>(&W[(size_t)(k0 + wK) * N + col]);
            } else {
                float tmp[4] = {0.f, 0.f, 0.f, 0.f};
                for (int j = 0; j < 4; j++)
                    if (col + j < N) tmp[j] = W[(size_t)(k0 + wK) * N + col + j];
                v = make_float4(tmp[0], tmp[1], tmp[2], tmp[3]);
            }
            *reinterpret_cast<float4*>(&Wsm[wK][wC]) = v;
        }
        __syncthreads();
#pragma unroll
        for (int kk = 0; kk < BK; kk++) {
            float a[8], b[4];
#pragma unroll
            for (int i = 0; i < 8; i++) a[i] = As[kk][rBase + i];
#pragma unroll
            for (int j = 0; j < 4; j++) b[j] = Wsm[kk][cBase + j];
#pragma unroll
            for (int i = 0; i < 8; i++)
#pragma unroll
                for (int j = 0; j < 4; j++) acc[i][j] = fmaf(a[i], b[j], acc[i][j]);
        }
        __syncthreads();
    }
#pragma unroll
    for (int i = 0; i < 8; i++) {
        int row = rowBlock + rBase + i;
#pragma unroll
        for (int j = 0; j < 4; j++) {
            int col = colBlock + cBase + j;
            if (col < N) {
                float v = acc[i][j] + bias[col];
                if (doRelu) v = fmaxf(v, 0.f);
                C[(size_t)row * N + col] = v;
            }
        }
    }
}

// ---------------- pass A ----------------
__global__ __launch_bounds__(128) void passA(
    const float* __restrict__ z, const float* __restrict__ t1,
    const float* __restrict__ clus, float* __restrict__ q,
    int* __restrict__ pred, float* __restrict__ scon,
    float* __restrict__ out, int out_size)
{
    __shared__ float cs[K_C * NZ_C];
    const int tid = threadIdx.x;
    for (int i = tid; i < K_C * NZ_C; i += 128) cs[i] = clus[i];
    __syncthreads();

    const int n = blockIdx.x * 128 + tid;
    if (n >= N_PTS) return;

    const float tx = t1[n * 3 + 0] * 0.01f;
    const float ty = t1[n * 3 + 1] * 0.01f;
    const float tz = t1[n * 3 + 2] * 0.01f;
    const float cm = tx * ty * tz * 0.99f + 1.0f;

    float zp[NZ_C];
    const float* zr = &z[(size_t)n * NZ_C];
    float mean = 0.f;
#pragma unroll
    for (int i = 0; i < NZ_C; i++) { zp[i] = zr[i] * cm; mean += zp[i]; }
    mean *= (1.0f / NZ_C);
    float var = 0.f;
#pragma unroll
    for (int i = 0; i < NZ_C; i++) { float dd = zp[i] - mean; var += dd * dd; }
    var *= (1.0f / (NZ_C - 1));
    const float invstd = 1.0f / sqrtf(var);
#pragma unroll
    for (int i = 0; i < NZ_C; i++) zp[i] = (zp[i] - mean) * invstd;

    float qsum = 0.f;
    float best = -1.f;
    int bestk = 0;
    for (int k = 0; k < K_C; k++) {
        const float* c = &cs[k * NZ_C];
        float dsum = 0.f;
#pragma unroll
        for (int i = 0; i < NZ_C; i++) { float df = zp[i] - c[i]; dsum = fmaf(df, df, dsum); }
        float qr = EPS_C + dsum;
        q[(size_t)k * N_PTS + n] = qr;
        qsum += qr;
        if (qr > best) { best = qr; bestk = k; }
    }
    const float inv = 1.0f / qsum;
    float s = 0.f;
    for (int k = 0; k < K_C; k++) {
        float qn = q[(size_t)k * N_PTS + n] * inv;
        q[(size_t)k * N_PTS + n] = qn;
        float l = logf(qn);
        float t = 1.0f - qn;
        float neg_temp = t * t * (-l) * (float)N_PTS;
        s += 1.0f / sqrtf(neg_temp);
    }
    pred[n] = bestk;
    scon[n] = s;
    if (n < out_size) out[n] = (float)bestk;
    atomicAdd(&g_cnt[bestk], 1);
}

// ---------------- reductions ----------------
__global__ void ureduce(const float* __restrict__ q) {
    __shared__ float sh[256];
    const int k = blockIdx.x;
    float s = 0.f;
    for (int n = threadIdx.x; n < N_PTS; n += 256) s += q[(size_t)k * N_PTS + n];
    sh[threadIdx.x] = s;
    __syncthreads();
    for (int o = 128; o > 0; o >>= 1) {
        if (threadIdx.x < o) sh[threadIdx.x] += sh[threadIdx.x + o];
        __syncthreads();
    }
    if (threadIdx.x == 0) g_u[k] = sh[0];
}

__global__ void sreduce(const float* __restrict__ scon) {
    __shared__ float sh[256];
    float s = 0.f;
    for (int n = threadIdx.x; n < N_PTS; n += 256) s += scon[n];
    sh[threadIdx.x] = s;
    __syncthreads();
    for (int o = 128; o > 0; o >>= 1) {
        if (threadIdx.x < o) sh[threadIdx.x] += sh[threadIdx.x + o];
        __syncthreads();
    }
    if (threadIdx.x == 0) g_S = sh[0];
}

__global__ void passB(const float* __restrict__ clus) {
    __shared__ float sh[256];
    const int tid = threadIdx.x;
    float s = 0.f;
    for (int p = tid; p < K_C * K_C; p += 256) {
        int i = p / K_C, j = p - i * K_C;
        const float* a = &clus[i * NZ_C];
        const float* b = &clus[j * NZ_C];
        float dsum = 0.f;
#pragma unroll
        for (int t = 0; t < NZ_C; t++) { float df = a[t] - b[t]; dsum = fmaf(df, df, dsum); }
        s += dsum;
    }
    sh[tid] = s;
    __syncthreads();
    for (int o = 128; o > 0; o >>= 1) {
        if (tid < o) sh[tid] += sh[tid + o];
        __syncthreads();
    }
    if (tid == 0) {
        float md = sh[0] / (float)(K_C * K_C - K_C);
        g_uloss = 0.01f / md;

        float un[K_C], vn[K_C];
        float um = 0.f;
        for (int k = 0; k < K_C; k++) um += g_u[k];
        um /= (float)K_C;
        float uv = 0.f;
        for (int k = 0; k < K_C; k++) { float dd = g_u[k] - um; uv += dd * dd; }
        uv /= (float)(K_C - 1);
        float uis = 1.0f / sqrtf(uv);
        for (int k = 0; k < K_C; k++) un[k] = (g_u[k] - um) * uis;

        float S = g_S;
        float vm = 0.f;
        for (int k = 0; k < K_C; k++) {
            float nc = (g_cnt[k] > 0) ? (float)g_cnt[k] : 1.0f;
            vn[k] = sqrtf(nc) * S;
            vm += vn[k];
        }
        vm /= (float)K_C;
        float vv = 0.f;
        for (int k = 0; k < K_C; k++) { float dd = vn[k] - vm; vv += dd * dd; }
        vv /= (float)(K_C - 1);
        float vis = 1.0f / sqrtf(vv);
        for (int k = 0; k < K_C; k++) vn[k] = (vn[k] - vm) * vis;

        float umin = un[0], vmin = vn[0];
        for (int k = 1; k < K_C; k++) {
            umin = fminf(umin, un[k]);
            vmin = fminf(vmin, vn[k]);
        }
        for (int k = 0; k < K_C; k++) {
            g_f[k] = (un[k] - umin + 0.001f) + (vn[k] - vmin + 0.001f) + 1.0f;
        }
    }
}

__global__ __launch_bounds__(128) void passC(const float* __restrict__ q,
                                             float* __restrict__ klp) {
    __shared__ float fsh[K_C];
    __shared__ float sh[128];
    const int tid = threadIdx.x;
    for (int i = tid; i < K_C; i += 128) fsh[i] = g_f[i];
    __syncthreads();
    const int n = blockIdx.x * 128 + tid;
    float kl = 0.f;
    float ws = 0.f;
    for (int k = 0; k < K_C; k++) {
        float qv = q[(size_t)k * N_PTS + n];
        ws += qv * qv / fsh[k];
    }
    float inv = 1.0f / ws;
    for (int k = 0; k < K_C; k++) {
        float qv = q[(size_t)k * N_PTS + n];
        float p = qv * qv / fsh[k] * inv;
        kl += p * (logf(p) - logf(qv));
    }
    sh[tid] = kl;
    __syncthreads();
    for (int o = 64; o > 0; o >>= 1) {
        if (tid < o) sh[tid] += sh[tid + o];
        __syncthreads();
    }
    if (tid == 0) klp[blockIdx.x] = sh[0];
}

__global__ void finalk(float* __restrict__ out, int out_size) {
    __shared__ float sh[256];
    __shared__ float tot[2];
    const int tid = threadIdx.x;
    float s = 0.f;
    for (int i = tid; i < MSE_PARTIALS; i += 256) s += g_msep[i];
    sh[tid] = s;
    __syncthreads();
    for (int o = 128; o > 0; o >>= 1) {
        if (tid < o) sh[tid] += sh[tid + o];
        __syncthreads();
    }
    if (tid == 0) tot[0] = sh[0];
    __syncthreads();
    s = 0.f;
    for (int i = tid; i < MBLK; i += 256) s += g_klp[i];
    sh[tid] = s;
    __syncthreads();
    for (int o = 128; o > 0; o >>= 1) {
        if (tid < o) sh[tid] += sh[tid + o];
        __syncthreads();
    }
    if (tid == 0) tot[1] = sh[0];
    __syncthreads();
    if (tid == 0) {
        float re_loss = tot[0] / ((float)N_PTS * (float)N_IN_C);
        float kl_loss = tot[1] / ((float)N_PTS * (float)K_C) * 0.01f;
        float loss = kl_loss + re_loss + g_uloss;
        if (out_size > N_PTS) out[N_PTS] = loss;
    }
}

// ---------------- launch ----------------
extern "C" void kernel_launch(void* const* d_in, const int* in_sizes, int n_in,
                              void* d_out, int out_size) {
    const float* x    = (const float*)d_in[0];
    const float* t1   = (const float*)d_in[1];
    const float* clus = (const float*)d_in[2];
    const float* We1  = (const float*)d_in[3];
    const float* be1  = (const float*)d_in[4];
    const float* We2  = (const float*)d_in[5];
    const float* be2  = (const float*)d_in[6];
    const float* We3  = (const float*)d_in[7];
    const float* be3  = (const float*)d_in[8];
    const float* Wz   = (const float*)d_in[9];
    const float* bz   = (const float*)d_in[10];
    const float* Wd1  = (const float*)d_in[11];
    const float* bd1  = (const float*)d_in[12];
    const float* Wd2  = (const float*)d_in[13];
    const float* bd2  = (const float*)d_in[14];
    const float* Wd3  = (const float*)d_in[15];
    const float* bd3  = (const float*)d_in[16];
    const float* Wxb  = (const float*)d_in[17];
    const float* bxb  = (const float*)d_in[18];
    float* out = (float*)d_out;

    float *bufA, *bufB, *cA0, *cA1, *cA2, *cB0, *cB1, *cB2;
    float *zbuf, *qbuf, *scon, *msep, *klp;
    int *pred;
    cudaGetSymbolAddress((void**)&bufA, g_bufA);
    cudaGetSymbolAddress((void**)&bufB, g_bufB);
    cudaGetSymbolAddress((void**)&cA0, g_cA0);
    cudaGetSymbolAddress((void**)&cA1, g_cA1);
    cudaGetSymbolAddress((void**)&cA2, g_cA2);
    cudaGetSymbolAddress((void**)&cB0, g_cB0);
    cudaGetSymbolAddress((void**)&cB1, g_cB1);
    cudaGetSymbolAddress((void**)&cB2, g_cB2);
    cudaGetSymbolAddress((void**)&zbuf, g_zbuf);
    cudaGetSymbolAddress((void**)&qbuf, g_q);
    cudaGetSymbolAddress((void**)&pred, g_pred);
    cudaGetSymbolAddress((void**)&scon, g_Scon);
    cudaGetSymbolAddress((void**)&msep, g_msep);
    cudaGetSymbolAddress((void**)&klp,  g_klp);

    const int DS3 = 3 * 8192 * 2 * 4;   // 196608 B
    const int DS2 = 2 * 8192 * 2 * 4;   // 131072 B
    cudaFuncSetAttribute(mma_pipe<3, 0>, cudaFuncAttributeMaxDynamicSharedMemorySize, DS3);
    cudaFuncSetAttribute(mma_pipe<2, 0>, cudaFuncAttributeMaxDynamicSharedMemorySize, DS2);
    cudaFuncSetAttribute(mma_pipe<2, 1>, cudaFuncAttributeMaxDynamicSharedMemorySize, DS2);

    init_kernel<<<1, 128>>>();

    auto blocksFor = [](int elems) { return (elems + 255) / 256; };

    // ---- encoder (3-way split, 6-term) ----
    splitA<3><<<blocksFor(N_PTS * N_IN_C), 256>>>(x, cA0, cA1, cA2, N_PTS * N_IN_C, 10);
    splitB<3><<<blocksFor(N_IN_C * E1_C), 256>>>(We1, cB0, cB1, cB2, N_IN_C * E1_C, 9, N_IN_C);
    mma_pipe<3, 0><<<dim3(E1_C / 128, MBLK), 256, DS3>>>(cA0, cA1, cA2, cB0, cB1, cB2,
        be1, bufA, nullptr, nullptr, N_IN_C, E1_C);

    splitA<3><<<blocksFor(N_PTS * E1_C), 256>>>(bufA, cA0, cA1, cA2, N_PTS * E1_C, 9);
    splitB<3><<<blocksFor(E1_C * E2_C), 256>>>(We2, cB0, cB1, cB2, E1_C * E2_C, 9, E1_C);
    mma_pipe<3, 0><<<dim3(E2_C / 128, MBLK), 256, DS3>>>(cA0, cA1, cA2, cB0, cB1, cB2,
        be2, bufB, nullptr, nullptr, E1_C, E2_C);

    splitA<3><<<blocksFor(N_PTS * E2_C), 256>>>(bufB, cA0, cA1, cA2, N_PTS * E2_C, 9);
    splitB<3><<<blocksFor(E2_C * E3_C), 256>>>(We3, cB0, cB1, cB2, E2_C * E3_C, 11, E2_C);
    mma_pipe<3, 0><<<dim3(E3_C / 128, MBLK), 256, DS3>>>(cA0, cA1, cA2, cB0, cB1, cB2,
        be3, bufA, nullptr, nullptr, E2_C, E3_C);

    // z layer (scalar fp32, N=32)
    gemm_relu<<<dim3(1, N_PTS / BM), 256>>>(bufA, Wz, bz, zbuf, N_PTS, E3_C, NZ_C, 0);

    // ---- decoder (2-way split, 3-term) ----
    splitA<2><<<blocksFor(N_PTS * NZ_C), 256>>>(zbuf, cA0, cA1, nullptr, N_PTS * NZ_C, 5);
    splitB<2><<<blocksFor(NZ_C * D1_C), 256>>>(Wd1, cB0, cB1, nullptr, NZ_C * D1_C, 11, NZ_C);
    mma_pipe<2, 0><<<dim3(D1_C / 128, MBLK), 256, DS2>>>(cA0, cA1, nullptr, cB0, cB1, nullptr,
        bd1, bufB, nullptr, nullptr, NZ_C, D1_C);

    splitA<2><<<blocksFor(N_PTS * D1_C), 256>>>(bufB, cA0, cA1, nullptr, N_PTS * D1_C, 11);
    splitB<2><<<blocksFor(D1_C * D2_C), 256>>>(Wd2, cB0, cB1, nullptr, D1_C * D2_C, 9, D1_C);
    mma_pipe<2, 0><<<dim3(D2_C / 128, MBLK), 256, DS2>>>(cA0, cA1, nullptr, cB0, cB1, nullptr,
        bd2, bufA, nullptr, nullptr, D1_C, D2_C);

    splitA<2><<<blocksFor(N_PTS * D2_C), 256>>>(bufA, cA0, cA1, nullptr, N_PTS * D2_C, 9);
    splitB<2><<<blocksFor(D2_C * D3_C), 256>>>(Wd3, cB0, cB1, nullptr, D2_C * D3_C, 9, D2_C);
    mma_pipe<2, 0><<<dim3(D3_C / 128, MBLK), 256, DS2>>>(cA0, cA1, nullptr, cB0, cB1, nullptr,
        bd3, bufB, nullptr, nullptr, D2_C, D3_C);

    splitA<2><<<blocksFor(N_PTS * D3_C), 256>>>(bufB, cA0, cA1, nullptr, N_PTS * D3_C, 9);
    splitB<2><<<blocksFor(D3_C * N_IN_C), 256>>>(Wxb, cB0, cB1, nullptr, D3_C * N_IN_C, 10, D3_C);
    mma_pipe<2, 1><<<dim3(N_IN_C / 128, MBLK), 256, DS2>>>(cA0, cA1, nullptr, cB0, cB1, nullptr,
        bxb, nullptr, x, msep, D3_C, N_IN_C);

    // ---- clustering + losses ----
    passA<<<MBLK, 128>>>(zbuf, t1, clus, qbuf, pred, scon, out, out_size);
    ureduce<<<K_C, 256>>>(qbuf);
    sreduce<<<1, 256>>>(scon);
    passB<<<1, 256>>>(clus);
    passC<<<MBLK, 128>>>(qbuf, klp);
    finalk<<<1, 256>>>(out, out_size);
}

// round 8
// speedup vs baseline: 1.3858x; 1.3060x over previous
#include <cuda_runtime.h>
#include <cuda_bf16.h>
#include <math.h>
#include <stdint.h>
#include <string.h>

// ---------------- problem constants ----------------
#define N_PTS   29696
#define N_IN_C  1024
#define E1_C    512
#define E2_C    512
#define E3_C    2048
#define NZ_C    32
#define D1_C    2048
#define D2_C    512
#define D3_C    512
#define K_C     100
#define EPS_C   1e-5f

#define MBLK    (N_PTS / 128)                   // 232
#define MSE_PARTIALS (MBLK * (N_IN_C / 128))    // 1856

// z-layer scalar GEMM tiling
#define BM 128
#define BN 64
#define BK 16

// ---------------- scratch ----------------
__device__ float g_bufA[(size_t)N_PTS * 2048];
__device__ float g_bufB[(size_t)N_PTS * 2048];
// bf16-pair component buffers (u32 = 2 packed bf16), fragment-major layouts
__device__ uint32_t g_cA0[(size_t)N_PTS * 1024];   // A comps 0,1: up to K=2048
__device__ uint32_t g_cA1[(size_t)N_PTS * 1024];
__device__ uint32_t g_cA2[(size_t)N_PTS * 512];    // A comps 2,3: encoder only (K<=1024)
__device__ uint32_t g_cA3[(size_t)N_PTS * 512];
__device__ uint32_t g_cB0[2048 * 1024];
__device__ uint32_t g_cB1[2048 * 1024];
__device__ uint32_t g_cB2[2048 * 1024];
__device__ uint32_t g_cB3[2048 * 1024];
__device__ float g_zbuf[(size_t)N_PTS * NZ_C];
__device__ float g_q[(size_t)K_C * N_PTS];
__device__ int   g_pred[N_PTS];
__device__ float g_Scon[N_PTS];
__device__ float g_u[K_C];
__device__ float g_f[K_C];
__device__ int   g_cnt[K_C];
__device__ float g_S;
__device__ float g_uloss;
__device__ float g_msep[MSE_PARTIALS];
__device__ float g_klp[MBLK];

__global__ void init_kernel() {
    int t = threadIdx.x;
    if (t < K_C) g_cnt[t] = 0;
}

// ---------------- helpers ----------------
__device__ __forceinline__ uint16_t bf16b(float x) {
    __nv_bfloat16 h = __float2bfloat16_rn(x);
    return *reinterpret_cast<uint16_t*>(&h);
}
__device__ __forceinline__ float bf2f(uint16_t b) {
    __nv_bfloat16 h;
    memcpy(&h, &b, 2);
    return __bfloat162float(h);
}
__device__ __forceinline__ void mma16(float* d, const uint32_t* a, const uint32_t* b) {
    asm volatile(
        "mma.sync.aligned.m16n8k16.row.col.f32.bf16.bf16.f32 "
        "{%0,%1,%2,%3}, {%4,%5,%6,%7}, {%8,%9}, {%0,%1,%2,%3};"
        : "+f"(d[0]), "+f"(d[1]), "+f"(d[2]), "+f"(d[3])
        : "r"(a[0]), "r"(a[1]), "r"(a[2]), "r"(a[3]), "r"(b[0]), "r"(b[1]));
}
__device__ __forceinline__ void cpa16(uint32_t dst_smem, const void* src) {
    asm volatile("cp.async.cg.shared.global [%0], [%1], 16;"
                 :: "r"(dst_smem), "l"(__cvta_generic_to_global(src)));
}

// ---------------- split kernels (fp32 -> NSPLIT bf16 components, fragment-major) ----------------
// A comp layout per 16x16 (m x k) tile: 32 lanes x 4 u32.
// lane=(m&7)*4+((k&7)>>1), slot=((m>>3)&1)+2*((k&15)>>3), pair=k&1 (low 16 bits = even k)
template <int NSPLIT>
__global__ void splitA_bf(const float* __restrict__ src,
                          uint32_t* __restrict__ c0, uint32_t* __restrict__ c1,
                          uint32_t* __restrict__ c2, uint32_t* __restrict__ c3,
                          int MK2, int logK) {
    int idx = blockIdx.x * 256 + threadIdx.x;
    if (idx >= MK2) return;
    const int K2 = 1 << (logK - 1);
    int k2 = idx & (K2 - 1);
    int m = idx >> (logK - 1);
    int k = k2 << 1;
    float v0 = src[((size_t)m << logK) + k];
    float v1 = src[((size_t)m << logK) + k + 1];
    uint16_t a0[4], a1[4];
    float r = v0;
#pragma unroll
    for (int c = 0; c < NSPLIT; c++) { uint16_t b = bf16b(r); a0[c] = b; r -= bf2f(b); }
    r = v1;
#pragma unroll
    for (int c = 0; c < NSPLIT; c++) { uint16_t b = bf16b(r); a1[c] = b; r -= bf2f(b); }
    const int Ktiles = 1 << (logK - 4);
    int klo = k & 15;
    int tile = (m >> 4) * Ktiles + (k >> 4);
    int lane = (m & 7) * 4 + ((klo & 7) >> 1);
    int slot = ((m >> 3) & 1) + ((klo >> 3) << 1);
    size_t off = (size_t)tile * 128 + lane * 4 + slot;
    c0[off] = (uint32_t)a0[0] | ((uint32_t)a1[0] << 16);
    if (NSPLIT >= 2) c1[off] = (uint32_t)a0[1] | ((uint32_t)a1[1] << 16);
    if (NSPLIT >= 3) c2[off] = (uint32_t)a0[2] | ((uint32_t)a1[2] << 16);
    if (NSPLIT >= 4) c3[off] = (uint32_t)a0[3] | ((uint32_t)a1[3] << 16);
}

// B comp layout per 8x16 (n x k) tile: 32 lanes x 2 u32. from W[k][n] row-major KxN
// lane=(n&7)*4+((k&7)>>1), slot=(k&15)>>3, pair=k&1
template <int NSPLIT>
__global__ void splitB_bf(const float* __restrict__ W,
                          uint32_t* __restrict__ c0, uint32_t* __restrict__ c1,
                          uint32_t* __restrict__ c2, uint32_t* __restrict__ c3,
                          int KN2, int logN, int K) {
    int idx = blockIdx.x * 256 + threadIdx.x;
    if (idx >= KN2) return;
    int n = idx & ((1 << logN) - 1);
    int k2 = idx >> logN;
    int k = k2 << 1;
    float v0 = W[((size_t)k << logN) + n];
    float v1 = W[((size_t)(k + 1) << logN) + n];
    uint16_t a0[4], a1[4];
    float r = v0;
#pragma unroll
    for (int c = 0; c < NSPLIT; c++) { uint16_t b = bf16b(r); a0[c] = b; r -= bf2f(b); }
    r = v1;
#pragma unroll
    for (int c = 0; c < NSPLIT; c++) { uint16_t b = bf16b(r); a1[c] = b; r -= bf2f(b); }
    const int Ktiles = K >> 4;
    int klo = k & 15;
    int tile = (n >> 3) * Ktiles + (k >> 4);
    int lane = (n & 7) * 4 + ((klo & 7) >> 1);
    int slot = klo >> 3;
    size_t off = (size_t)tile * 64 + lane * 2 + slot;
    c0[off] = (uint32_t)a0[0] | ((uint32_t)a1[0] << 16);
    if (NSPLIT >= 2) c1[off] = (uint32_t)a0[1] | ((uint32_t)a1[1] << 16);
    if (NSPLIT >= 3) c2[off] = (uint32_t)a0[2] | ((uint32_t)a1[2] << 16);
    if (NSPLIT >= 4) c3[off] = (uint32_t)a0[3] | ((uint32_t)a1[3] << 16);
}

// ---------------- 3-stage pipelined split-bf16 mma GEMM ----------------
// Block tile 128x128, K-chunk 32 (2 mma k-steps of 16). 8 warps (2x4), warp tile 64x32.
// Stage u32 size = NSPLIT*4096 (A NSPLIT*2048 + B NSPLIT*2048)
template <int NSPLIT, int MODE>
__global__ void __launch_bounds__(256, 1) mma_bf(
    const uint32_t* __restrict__ A0, const uint32_t* __restrict__ A1,
    const uint32_t* __restrict__ A2, const uint32_t* __restrict__ A3,
    const uint32_t* __restrict__ B0, const uint32_t* __restrict__ B1,
    const uint32_t* __restrict__ B2, const uint32_t* __restrict__ B3,
    const float* __restrict__ bias, float* __restrict__ C,
    const float* __restrict__ Xref, float* __restrict__ partial,
    int K, int N)
{
    extern __shared__ uint32_t smu[];
    const int STAGE_U = NSPLIT * 4096;
    const int tid = threadIdx.x;
    const int wid = tid >> 5;
    const int lane = tid & 31;
    const int warpM = wid >> 2;
    const int warpN = wid & 3;
    const int rowBlock = blockIdx.y * 128;
    const int colBlock = blockIdx.x * 128;
    const int rowTile = blockIdx.y * 8;
    const int colTile = blockIdx.x * 16;
    const int Ktiles = K >> 4;
    const int nch = K >> 5;

    const uint32_t* Ac[4] = { A0, A1, A2, A3 };
    const uint32_t* Bc[4] = { B0, B1, B2, B3 };
    const uint32_t smem_base = (uint32_t)__cvta_generic_to_shared(smu);

    // term lists (a-comp, b-comp), smallest weight first
    constexpr int NT = (NSPLIT == 4) ? 10 : 3;
    constexpr int TA4[10] = {0, 3, 1, 2, 2, 0, 1, 1, 0, 0};
    constexpr int TB4[10] = {3, 0, 2, 1, 0, 2, 1, 0, 1, 0};
    constexpr int TA2[3]  = {1, 0, 0};
    constexpr int TB2[3]  = {0, 1, 0};

    float d[4][4][4];
#pragma unroll
    for (int mt = 0; mt < 4; mt++)
#pragma unroll
        for (int nt = 0; nt < 4; nt++)
#pragma unroll
            for (int i = 0; i < 4; i++) d[mt][nt][i] = 0.f;

    auto copy_stage = [&](int s, int c) {
        const uint32_t sb = smem_base + (uint32_t)(s * STAGE_U) * 4u;
        // A: NSPLIT*512 16B ops
#pragma unroll
        for (int j = 0; j < NSPLIT * 2; j++) {
            int o = j * 256 + tid;
            int comp = o >> 9;
            int rem = o & 511;
            int mt = rem >> 6;
            int w = (rem & 63) * 4;
            cpa16(sb + (uint32_t)(comp * 2048 + mt * 256 + w) * 4u,
                  Ac[comp] + ((size_t)(rowTile + mt) * Ktiles + 2 * c) * 128 + w);
        }
        // B: NSPLIT*512 16B ops
#pragma unroll
        for (int j = 0; j < NSPLIT * 2; j++) {
            int o = j * 256 + tid;
            int comp = o >> 9;
            int rem = o & 511;
            int nt = rem >> 5;
            int w = (rem & 31) * 4;
            cpa16(sb + (uint32_t)(NSPLIT * 2048 + comp * 2048 + nt * 128 + w) * 4u,
                  Bc[comp] + ((size_t)(colTile + nt) * Ktiles + 2 * c) * 64 + w);
        }
    };

    auto compute_stage = [&](int s) {
        const uint32_t* sA = smu + s * STAGE_U;
        const uint32_t* sB = sA + NSPLIT * 2048;
#pragma unroll
        for (int ks = 0; ks < 2; ks++) {
            uint32_t bf[NSPLIT][4][2];
#pragma unroll
            for (int nt = 0; nt < 4; nt++)
#pragma unroll
                for (int cc = 0; cc < NSPLIT; cc++) {
                    const uint32_t* p = &sB[cc * 2048 + (warpN * 4 + nt) * 128 + ks * 64 + lane * 2];
                    bf[cc][nt][0] = p[0];
                    bf[cc][nt][1] = p[1];
                }
#pragma unroll
            for (int mt = 0; mt < 4; mt++) {
                uint32_t af[NSPLIT][4];
#pragma unroll
                for (int cc = 0; cc < NSPLIT; cc++) {
                    const uint32_t* p = &sA[cc * 2048 + (warpM * 4 + mt) * 256 + ks * 128 + lane * 4];
                    af[cc][0] = p[0]; af[cc][1] = p[1]; af[cc][2] = p[2]; af[cc][3] = p[3];
                }
#pragma unroll
                for (int nt = 0; nt < 4; nt++) {
#pragma unroll
                    for (int t = 0; t < NT; t++) {
                        int ta = (NSPLIT == 4) ? TA4[t] : TA2[t];
                        int tb = (NSPLIT == 4) ? TB4[t] : TB2[t];
                        mma16(d[mt][nt], af[ta], bf[tb][nt]);
                    }
                }
            }
        }
    };

    // 3-stage pipelined mainloop
    const int pre = (nch < 3) ? nch : 3;
    for (int s = 0; s < pre; s++) {
        copy_stage(s, s);
        asm volatile("cp.async.commit_group;" ::: "memory");
    }
    for (int c = 0; c < nch; c++) {
        int ahead = nch - c - 1;
        if (ahead >= 2)      asm volatile("cp.async.wait_group 2;" ::: "memory");
        else if (ahead == 1) asm volatile("cp.async.wait_group 1;" ::: "memory");
        else                 asm volatile("cp.async.wait_group 0;" ::: "memory");
        __syncthreads();
        compute_stage(c % 3);
        if (c + 3 < nch) {
            __syncthreads();
            copy_stage(c % 3, c + 3);
            asm volatile("cp.async.commit_group;" ::: "memory");
        }
    }

    // ---- epilogue (identical mapping to proven R6/R7) ----
    float2 bb[4];
#pragma unroll
    for (int nt = 0; nt < 4; nt++)
        bb[nt] = *reinterpret_cast<const float2*>(
            &bias[colBlock + warpN * 32 + nt * 8 + (lane & 3) * 2]);

    if (MODE == 0) {
#pragma unroll
        for (int mt = 0; mt < 4; mt++) {
            const int r0 = rowBlock + warpM * 64 + mt * 16 + (lane >> 2);
#pragma unroll
            for (int nt = 0; nt < 4; nt++) {
                const int col = colBlock + warpN * 32 + nt * 8 + (lane & 3) * 2;
                float2 v0, v1;
                v0.x = fmaxf(d[mt][nt][0] + bb[nt].x, 0.f);
                v0.y = fmaxf(d[mt][nt][1] + bb[nt].y, 0.f);
                v1.x = fmaxf(d[mt][nt][2] + bb[nt].x, 0.f);
                v1.y = fmaxf(d[mt][nt][3] + bb[nt].y, 0.f);
                *reinterpret_cast<float2*>(&C[(size_t)r0 * N + col]) = v0;
                *reinterpret_cast<float2*>(&C[(size_t)(r0 + 8) * N + col]) = v1;
            }
        }
    } else {
        float msum = 0.f;
#pragma unroll
        for (int mt = 0; mt < 4; mt++) {
            const int r0 = rowBlock + warpM * 64 + mt * 16 + (lane >> 2);
#pragma unroll
            for (int nt = 0; nt < 4; nt++) {
                const int col = colBlock + warpN * 32 + nt * 8 + (lane & 3) * 2;
                float2 x0 = *reinterpret_cast<const float2*>(&Xref[(size_t)r0 * N + col]);
                float2 x1 = *reinterpret_cast<const float2*>(&Xref[(size_t)(r0 + 8) * N + col]);
                float e;
                e = d[mt][nt][0] + bb[nt].x - x0.x; msum = fmaf(e, e, msum);
                e = d[mt][nt][1] + bb[nt].y - x0.y; msum = fmaf(e, e, msum);
                e = d[mt][nt][2] + bb[nt].x - x1.x; msum = fmaf(e, e, msum);
                e = d[mt][nt][3] + bb[nt].y - x1.y; msum = fmaf(e, e, msum);
            }
        }
        __syncthreads();
        float* red = reinterpret_cast<float*>(smu);
        red[tid] = msum;
        __syncthreads();
        for (int o = 128; o > 0; o >>= 1) {
            if (tid < o) red[tid] += red[tid + o];
            __syncthreads();
        }
        if (tid == 0) partial[blockIdx.y * gridDim.x + blockIdx.x] = red[0];
    }
}

// ---------------- small-N fp32 scalar GEMM (z layer, N=32) ----------------
__global__ __launch_bounds__(256) void gemm_relu(
    const float* __restrict__ A, const float* __restrict__ W,
    const float* __restrict__ bias, float* __restrict__ C,
    int M, int K, int N, int doRelu)
{
    __shared__ float As[BK][BM];
    __shared__ float Wsm[BK][BN];
    const int tid = threadIdx.x;
    const int rowBlock = blockIdx.y * BM;
    const int colBlock = blockIdx.x * BN;
    const int tx = tid & 15;
    const int ty = tid >> 4;
    const int rBase = ty * 8;
    const int cBase = tx * 4;

    float acc[8][4];
#pragma unroll
    for (int i = 0; i < 8; i++)
#pragma unroll
        for (int j = 0; j < 4; j++) acc[i][j] = 0.f;

    const int aRow0 = tid >> 2;
    const int aF4   = tid & 3;
    const int wK    = tid >> 4;
    const int wC    = (tid & 15) * 4;

    for (int k0 = 0; k0 < K; k0 += BK) {
#pragma unroll
        for (int h = 0; h < 2; h++) {
            int r = aRow0 + h * 64;
            float4 v = *reinterpret_cast<const float4*>(
                &A[(size_t)(rowBlock + r) * K + k0 + aF4 * 4]);
            As[aF4 * 4 + 0][r] = v.x;
            As[aF4 * 4 + 1][r] = v.y;
            As[aF4 * 4 + 2][r] = v.z;
            As[aF4 * 4 + 3][r] = v.w;
        }
        {
            int col = colBlock + wC;
            float4 v = make_float4(0.f, 0.f, 0.f, 0.f);
            if (col + 3 < N) {
                v = *reinterpret_cast<const float4*>(&W[(size_t)(k0 + wK) * N + col]);
            } else {
                float tmp[4] = {0.f, 0.f, 0.f, 0.f};
                for (int j = 0; j < 4; j++)
                    if (col + j < N) tmp[j] = W[(size_t)(k0 + wK) * N + col + j];
                v = make_float4(tmp[0], tmp[1], tmp[2], tmp[3]);
            }
            *reinterpret_cast<float4*>(&Wsm[wK][wC]) = v;
        }
        __syncthreads();
#pragma unroll
        for (int kk = 0; kk < BK; kk++) {
            float a[8], b[4];
#pragma unroll
            for (int i = 0; i < 8; i++) a[i] = As[kk][rBase + i];
#pragma unroll
            for (int j = 0; j < 4; j++) b[j] = Wsm[kk][cBase + j];
#pragma unroll
            for (int i = 0; i < 8; i++)
#pragma unroll
                for (int j = 0; j < 4; j++) acc[i][j] = fmaf(a[i], b[j], acc[i][j]);
        }
        __syncthreads();
    }
#pragma unroll
    for (int i = 0; i < 8; i++) {
        int row = rowBlock + rBase + i;
#pragma unroll
        for (int j = 0; j < 4; j++) {
            int col = colBlock + cBase + j;
            if (col < N) {
                float v = acc[i][j] + bias[col];
                if (doRelu) v = fmaxf(v, 0.f);
                C[(size_t)row * N + col] = v;
            }
        }
    }
}

// ---------------- pass A ----------------
__global__ __launch_bounds__(128) void passA(
    const float* __restrict__ z, const float* __restrict__ t1,
    const float* __restrict__ clus, float* __restrict__ q,
    int* __restrict__ pred, float* __restrict__ scon,
    float* __restrict__ out, int out_size)
{
    __shared__ float cs[K_C * NZ_C];
    const int tid = threadIdx.x;
    for (int i = tid; i < K_C * NZ_C; i += 128) cs[i] = clus[i];
    __syncthreads();

    const int n = blockIdx.x * 128 + tid;
    if (n >= N_PTS) return;

    const float tx = t1[n * 3 + 0] * 0.01f;
    const float ty = t1[n * 3 + 1] * 0.01f;
    const float tz = t1[n * 3 + 2] * 0.01f;
    const float cm = tx * ty * tz * 0.99f + 1.0f;

    float zp[NZ_C];
    const float* zr = &z[(size_t)n * NZ_C];
    float mean = 0.f;
#pragma unroll
    for (int i = 0; i < NZ_C; i++) { zp[i] = zr[i] * cm; mean += zp[i]; }
    mean *= (1.0f / NZ_C);
    float var = 0.f;
#pragma unroll
    for (int i = 0; i < NZ_C; i++) { float dd = zp[i] - mean; var += dd * dd; }
    var *= (1.0f / (NZ_C - 1));
    const float invstd = 1.0f / sqrtf(var);
#pragma unroll
    for (int i = 0; i < NZ_C; i++) zp[i] = (zp[i] - mean) * invstd;

    float qsum = 0.f;
    float best = -1.f;
    int bestk = 0;
    for (int k = 0; k < K_C; k++) {
        const float* c = &cs[k * NZ_C];
        float dsum = 0.f;
#pragma unroll
        for (int i = 0; i < NZ_C; i++) { float df = zp[i] - c[i]; dsum = fmaf(df, df, dsum); }
        float qr = EPS_C + dsum;
        q[(size_t)k * N_PTS + n] = qr;
        qsum += qr;
        if (qr > best) { best = qr; bestk = k; }
    }
    const float inv = 1.0f / qsum;
    float s = 0.f;
    for (int k = 0; k < K_C; k++) {
        float qn = q[(size_t)k * N_PTS + n] * inv;
        q[(size_t)k * N_PTS + n] = qn;
        float l = logf(qn);
        float t = 1.0f - qn;
        float neg_temp = t * t * (-l) * (float)N_PTS;
        s += 1.0f / sqrtf(neg_temp);
    }
    pred[n] = bestk;
    scon[n] = s;
    if (n < out_size) out[n] = (float)bestk;
    atomicAdd(&g_cnt[bestk], 1);
}

// ---------------- reductions ----------------
__global__ void ureduce(const float* __restrict__ q) {
    __shared__ float sh[256];
    const int k = blockIdx.x;
    float s = 0.f;
    for (int n = threadIdx.x; n < N_PTS; n += 256) s += q[(size_t)k * N_PTS + n];
    sh[threadIdx.x] = s;
    __syncthreads();
    for (int o = 128; o > 0; o >>= 1) {
        if (threadIdx.x < o) sh[threadIdx.x] += sh[threadIdx.x + o];
        __syncthreads();
    }
    if (threadIdx.x == 0) g_u[k] = sh[0];
}

__global__ void sreduce(const float* __restrict__ scon) {
    __shared__ float sh[256];
    float s = 0.f;
    for (int n = threadIdx.x; n < N_PTS; n += 256) s += scon[n];
    sh[threadIdx.x] = s;
    __syncthreads();
    for (int o = 128; o > 0; o >>= 1) {
        if (threadIdx.x < o) sh[threadIdx.x] += sh[threadIdx.x + o];
        __syncthreads();
    }
    if (threadIdx.x == 0) g_S = sh[0];
}

__global__ void passB(const float* __restrict__ clus) {
    __shared__ float sh[256];
    const int tid = threadIdx.x;
    float s = 0.f;
    for (int p = tid; p < K_C * K_C; p += 256) {
        int i = p / K_C, j = p - i * K_C;
        const float* a = &clus[i * NZ_C];
        const float* b = &clus[j * NZ_C];
        float dsum = 0.f;
#pragma unroll
        for (int t = 0; t < NZ_C; t++) { float df = a[t] - b[t]; dsum = fmaf(df, df, dsum); }
        s += dsum;
    }
    sh[tid] = s;
    __syncthreads();
    for (int o = 128; o > 0; o >>= 1) {
        if (tid < o) sh[tid] += sh[tid + o];
        __syncthreads();
    }
    if (tid == 0) {
        float md = sh[0] / (float)(K_C * K_C - K_C);
        g_uloss = 0.01f / md;

        float un[K_C], vn[K_C];
        float um = 0.f;
        for (int k = 0; k < K_C; k++) um += g_u[k];
        um /= (float)K_C;
        float uv = 0.f;
        for (int k = 0; k < K_C; k++) { float dd = g_u[k] - um; uv += dd * dd; }
        uv /= (float)(K_C - 1);
        float uis = 1.0f / sqrtf(uv);
        for (int k = 0; k < K_C; k++) un[k] = (g_u[k] - um) * uis;

        float S = g_S;
        float vm = 0.f;
        for (int k = 0; k < K_C; k++) {
            float nc = (g_cnt[k] > 0) ? (float)g_cnt[k] : 1.0f;
            vn[k] = sqrtf(nc) * S;
            vm += vn[k];
        }
        vm /= (float)K_C;
        float vv = 0.f;
        for (int k = 0; k < K_C; k++) { float dd = vn[k] - vm; vv += dd * dd; }
        vv /= (float)(K_C - 1);
        float vis = 1.0f / sqrtf(vv);
        for (int k = 0; k < K_C; k++) vn[k] = (vn[k] - vm) * vis;

        float umin = un[0], vmin = vn[0];
        for (int k = 1; k < K_C; k++) {
            umin = fminf(umin, un[k]);
            vmin = fminf(vmin, vn[k]);
        }
        for (int k = 0; k < K_C; k++) {
            g_f[k] = (un[k] - umin + 0.001f) + (vn[k] - vmin + 0.001f) + 1.0f;
        }
    }
}

__global__ __launch_bounds__(128) void passC(const float* __restrict__ q,
                                             float* __restrict__ klp) {
    __shared__ float fsh[K_C];
    __shared__ float sh[128];
    const int tid = threadIdx.x;
    for (int i = tid; i < K_C; i += 128) fsh[i] = g_f[i];
    __syncthreads();
    const int n = blockIdx.x * 128 + tid;
    float kl = 0.f;
    float ws = 0.f;
    for (int k = 0; k < K_C; k++) {
        float qv = q[(size_t)k * N_PTS + n];
        ws += qv * qv / fsh[k];
    }
    float inv = 1.0f / ws;
    for (int k = 0; k < K_C; k++) {
        float qv = q[(size_t)k * N_PTS + n];
        float p = qv * qv / fsh[k] * inv;
        kl += p * (logf(p) - logf(qv));
    }
    sh[tid] = kl;
    __syncthreads();
    for (int o = 64; o > 0; o >>= 1) {
        if (tid < o) sh[tid] += sh[tid + o];
        __syncthreads();
    }
    if (tid == 0) klp[blockIdx.x] = sh[0];
}

__global__ void finalk(float* __restrict__ out, int out_size) {
    __shared__ float sh[256];
    __shared__ float tot[2];
    const int tid = threadIdx.x;
    float s = 0.f;
    for (int i = tid; i < MSE_PARTIALS; i += 256) s += g_msep[i];
    sh[tid] = s;
    __syncthreads();
    for (int o = 128; o > 0; o >>= 1) {
        if (tid < o) sh[tid] += sh[tid + o];
        __syncthreads();
    }
    if (tid == 0) tot[0] = sh[0];
    __syncthreads();
    s = 0.f;
    for (int i = tid; i < MBLK; i += 256) s += g_klp[i];
    sh[tid] = s;
    __syncthreads();
    for (int o = 128; o > 0; o >>= 1) {
        if (tid < o) sh[tid] += sh[tid + o];
        __syncthreads();
    }
    if (tid == 0) tot[1] = sh[0];
    __syncthreads();
    if (tid == 0) {
        float re_loss = tot[0] / ((float)N_PTS * (float)N_IN_C);
        float kl_loss = tot[1] / ((float)N_PTS * (float)K_C) * 0.01f;
        float loss = kl_loss + re_loss + g_uloss;
        if (out_size > N_PTS) out[N_PTS] = loss;
    }
}

// ---------------- launch ----------------
extern "C" void kernel_launch(void* const* d_in, const int* in_sizes, int n_in,
                              void* d_out, int out_size) {
    const float* x    = (const float*)d_in[0];
    const float* t1   = (const float*)d_in[1];
    const float* clus = (const float*)d_in[2];
    const float* We1  = (const float*)d_in[3];
    const float* be1  = (const float*)d_in[4];
    const float* We2  = (const float*)d_in[5];
    const float* be2  = (const float*)d_in[6];
    const float* We3  = (const float*)d_in[7];
    const float* be3  = (const float*)d_in[8];
    const float* Wz   = (const float*)d_in[9];
    const float* bz   = (const float*)d_in[10];
    const float* Wd1  = (const float*)d_in[11];
    const float* bd1  = (const float*)d_in[12];
    const float* Wd2  = (const float*)d_in[13];
    const float* bd2  = (const float*)d_in[14];
    const float* Wd3  = (const float*)d_in[15];
    const float* bd3  = (const float*)d_in[16];
    const float* Wxb  = (const float*)d_in[17];
    const float* bxb  = (const float*)d_in[18];
    float* out = (float*)d_out;

    float *bufA, *bufB, *zbuf, *qbuf, *scon, *msep, *klp;
    uint32_t *cA0, *cA1, *cA2, *cA3, *cB0, *cB1, *cB2, *cB3;
    int *pred;
    cudaGetSymbolAddress((void**)&bufA, g_bufA);
    cudaGetSymbolAddress((void**)&bufB, g_bufB);
    cudaGetSymbolAddress((void**)&cA0, g_cA0);
    cudaGetSymbolAddress((void**)&cA1, g_cA1);
    cudaGetSymbolAddress((void**)&cA2, g_cA2);
    cudaGetSymbolAddress((void**)&cA3, g_cA3);
    cudaGetSymbolAddress((void**)&cB0, g_cB0);
    cudaGetSymbolAddress((void**)&cB1, g_cB1);
    cudaGetSymbolAddress((void**)&cB2, g_cB2);
    cudaGetSymbolAddress((void**)&cB3, g_cB3);
    cudaGetSymbolAddress((void**)&zbuf, g_zbuf);
    cudaGetSymbolAddress((void**)&qbuf, g_q);
    cudaGetSymbolAddress((void**)&pred, g_pred);
    cudaGetSymbolAddress((void**)&scon, g_Scon);
    cudaGetSymbolAddress((void**)&msep, g_msep);
    cudaGetSymbolAddress((void**)&klp,  g_klp);

    const int DS4 = 3 * 4 * 4096 * 4;   // 196608 B
    const int DS2 = 3 * 2 * 4096 * 4;   //  98304 B
    cudaFuncSetAttribute(mma_bf<4, 0>, cudaFuncAttributeMaxDynamicSharedMemorySize, DS4);
    cudaFuncSetAttribute(mma_bf<2, 0>, cudaFuncAttributeMaxDynamicSharedMemorySize, DS2);
    cudaFuncSetAttribute(mma_bf<2, 1>, cudaFuncAttributeMaxDynamicSharedMemorySize, DS2);

    init_kernel<<<1, 128>>>();
    auto nb = [](int elems) { return (elems + 255) / 256; };

    // ---- encoder: 4-way bf16 split, 10 terms (~fp32-exact) ----
    splitA_bf<4><<<nb(N_PTS * 512), 256>>>(x, cA0, cA1, cA2, cA3, N_PTS * 512, 10);
    splitB_bf<4><<<nb(512 * E1_C), 256>>>(We1, cB0, cB1, cB2, cB3, 512 * E1_C, 9, N_IN_C);
    mma_bf<4, 0><<<dim3(E1_C / 128, MBLK), 256, DS4>>>(cA0, cA1, cA2, cA3, cB0, cB1, cB2, cB3,
        be1, bufA, nullptr, nullptr, N_IN_C, E1_C);

    splitA_bf<4><<<nb(N_PTS * 256), 256>>>(bufA, cA0, cA1, cA2, cA3, N_PTS * 256, 9);
    splitB_bf<4><<<nb(256 * E2_C), 256>>>(We2, cB0, cB1, cB2, cB3, 256 * E2_C, 9, E1_C);
    mma_bf<4, 0><<<dim3(E2_C / 128, MBLK), 256, DS4>>>(cA0, cA1, cA2, cA3, cB0, cB1, cB2, cB3,
        be2, bufB, nullptr, nullptr, E1_C, E2_C);

    splitA_bf<4><<<nb(N_PTS * 256), 256>>>(bufB, cA0, cA1, cA2, cA3, N_PTS * 256, 9);
    splitB_bf<4><<<nb(256 * E3_C), 256>>>(We3, cB0, cB1, cB2, cB3, 256 * E3_C, 11, E2_C);
    mma_bf<4, 0><<<dim3(E3_C / 128, MBLK), 256, DS4>>>(cA0, cA1, cA2, cA3, cB0, cB1, cB2, cB3,
        be3, bufA, nullptr, nullptr, E2_C, E3_C);

    // z layer (scalar fp32, N=32)
    gemm_relu<<<dim3(1, N_PTS / BM), 256>>>(bufA, Wz, bz, zbuf, N_PTS, E3_C, NZ_C, 0);

    // ---- decoder: 2-way bf16 split, 3 terms (loss-only consumer) ----
    splitA_bf<2><<<nb(N_PTS * 16), 256>>>(zbuf, cA0, cA1, nullptr, nullptr, N_PTS * 16, 5);
    splitB_bf<2><<<nb(16 * D1_C), 256>>>(Wd1, cB0, cB1, nullptr, nullptr, 16 * D1_C, 11, NZ_C);
    mma_bf<2, 0><<<dim3(D1_C / 128, MBLK), 256, DS2>>>(cA0, cA1, nullptr, nullptr, cB0, cB1, nullptr, nullptr,
        bd1, bufB, nullptr, nullptr, NZ_C, D1_C);

    splitA_bf<2><<<nb(N_PTS * 1024), 256>>>(bufB, cA0, cA1, nullptr, nullptr, N_PTS * 1024, 11);
    splitB_bf<2><<<nb(1024 * D2_C), 256>>>(Wd2, cB0, cB1, nullptr, nullptr, 1024 * D2_C, 9, D1_C);
    mma_bf<2, 0><<<dim3(D2_C / 128, MBLK), 256, DS2>>>(cA0, cA1, nullptr, nullptr, cB0, cB1, nullptr, nullptr,
        bd2, bufA, nullptr, nullptr, D1_C, D2_C);

    splitA_bf<2><<<nb(N_PTS * 256), 256>>>(bufA, cA0, cA1, nullptr, nullptr, N_PTS * 256, 9);
    splitB_bf<2><<<nb(256 * D3_C), 256>>>(Wd3, cB0, cB1, nullptr, nullptr, 256 * D3_C, 9, D2_C);
    mma_bf<2, 0><<<dim3(D3_C / 128, MBLK), 256, DS2>>>(cA0, cA1, nullptr, nullptr, cB0, cB1, nullptr, nullptr,
        bd3, bufB, nullptr, nullptr, D2_C, D3_C);

    splitA_bf<2><<<nb(N_PTS * 256), 256>>>(bufB, cA0, cA1, nullptr, nullptr, N_PTS * 256, 9);
    splitB_bf<2><<<nb(256 * N_IN_C), 256>>>(Wxb, cB0, cB1, nullptr, nullptr, 256 * N_IN_C, 10, D3_C);
    mma_bf<2, 1><<<dim3(N_IN_C / 128, MBLK), 256, DS2>>>(cA0, cA1, nullptr, nullptr, cB0, cB1, nullptr, nullptr,
        bxb, nullptr, x, msep, D3_C, N_IN_C);

    // ---- clustering + losses ----
    passA<<<MBLK, 128>>>(zbuf, t1, clus, qbuf, pred, scon, out, out_size);
    ureduce<<<K_C, 256>>>(qbuf);
    sreduce<<<1, 256>>>(scon);
    passB<<<1, 256>>>(clus);
    passC<<<MBLK, 128>>>(qbuf, klp);
    finalk<<<1, 256>>>(out, out_size);
}